// round 15
// baseline (speedup 1.0000x reference)
#include <cuda_runtime.h>
#include <cuda_fp16.h>
#include <math.h>

#define NN 50000
#define EE 800000

// ---------------- scratch (device globals; zero-initialized at load) ----------------
__device__ float  g_sae1[EE*4];   // a_edge (conv1) in CSR order
__device__ float  g_sae2[EE*4];   // a_edge (conv2) in CSR order
__device__ int    g_ssrc[EE];     // src node in CSR order
__device__ int    g_cnt[NN];      // invariant: zero at entry (scanc re-zeroes)
__device__ int    g_cur[NN];
__device__ int    g_rowptr[NN+1];
__device__ int    g_part[128];
__device__ int    g_scancnt;      // invariant: zero at entry (last block re-zeroes)
__device__ float  g_h0[NN*128];
__device__ float  g_h1[NN*128];
__device__ float  g_h2[NN*128];
__device__ __half g_xsh[NN*128];  // fp16 transformed features (gather source)
__device__ float  g_asrc[NN*4];
__device__ float  g_adst[NN*4];
__device__ float  g_M[32];        // [conv*16 + j*4 + h]
__device__ float  g_CW[5*384];    // collapsed classifier: cls_w @ jk_w
__device__ float  g_cb2[5];       // collapsed bias

// ---------------- helpers ----------------
__device__ __forceinline__ unsigned long long pack2(float x){
    unsigned long long r;
    unsigned int u = __float_as_uint(x);
    asm("mov.b64 %0, {%1, %1};" : "=l"(r) : "r"(u));
    return r;
}
__device__ __forceinline__ unsigned long long packf2(float a, float b){
    unsigned long long r;
    asm("mov.b64 %0, {%1, %2};" : "=l"(r) : "f"(a), "f"(b));
    return r;
}
__device__ __forceinline__ void fma2(unsigned long long& acc,
                                     unsigned long long a, unsigned long long b){
    asm("fma.rn.f32x2 %0, %1, %2, %0;" : "+l"(acc) : "l"(a), "l"(b));
}
__device__ __forceinline__ float lo2(unsigned long long v){
    unsigned int a, b;
    asm("mov.b64 {%0, %1}, %2;" : "=r"(a), "=r"(b) : "l"(v));
    return __uint_as_float(a);
}
__device__ __forceinline__ float hi2(unsigned long long v){
    unsigned int a, b;
    asm("mov.b64 {%0, %1}, %2;" : "=r"(a), "=r"(b) : "l"(v));
    return __uint_as_float(b);
}
__device__ __forceinline__ unsigned h2u(__half2 h){
    return *reinterpret_cast<unsigned*>(&h);
}

// ============ launch 1: hist + CW-prep + M-prep + node1, fused ============
#define B_HIST 782
#define B_CW   241
#define B_NODE1 1563

__global__ void __launch_bounds__(256) k_fused1(
        const int* __restrict__ ei,
        const float* __restrict__ le1, const float* __restrict__ ae1,
        const float* __restrict__ le2, const float* __restrict__ ae2,
        const float* __restrict__ cw,  const float* __restrict__ cb,
        const float* __restrict__ jkw, const float* __restrict__ jkb,
        const float* __restrict__ x,
        const float* __restrict__ pw, const float* __restrict__ pb,
        const float* __restrict__ lw,
        const float* __restrict__ asv, const float* __restrict__ adv){
    int b = blockIdx.x;
    if (b < B_HIST){
        int t = b*256 + threadIdx.x;
        if (t < EE/4){
            int4 d4 = ((const int4*)(ei+EE))[t];
            atomicAdd(&g_cnt[d4.x], 1);
            atomicAdd(&g_cnt[d4.y], 1);
            atomicAdd(&g_cnt[d4.z], 1);
            atomicAdd(&g_cnt[d4.w], 1);
        }
        return;
    }
    if (b < B_HIST + B_CW){
        int w = (b-B_HIST)*8 + (threadIdx.x >> 5);
        int lane = threadIdx.x & 31;
        if (w >= 5*385) return;
        int c = w / 385, j = w % 385;
        float4 a = *(const float4*)&cw[c*128 + lane*4];
        int d = lane*4;
        float s;
        if (j < 384){
            s = a.x*jkw[(d+0)*384+j] + a.y*jkw[(d+1)*384+j]
              + a.z*jkw[(d+2)*384+j] + a.w*jkw[(d+3)*384+j];
        } else {
            float4 bb = *(const float4*)&jkb[d];
            s = a.x*bb.x + a.y*bb.y + a.z*bb.z + a.w*bb.w;
        }
        #pragma unroll
        for (int o=16;o>0;o>>=1) s += __shfl_xor_sync(0xffffffffu, s, o);
        if (lane == 0){
            if (j < 384) g_CW[c*384+j] = s;
            else         g_cb2[c] = s + cb[c];
        }
        return;
    }
    if (b == B_HIST + B_CW){
        int t = threadIdx.x;
        if (t < 32){
            int which = t >> 4, j = (t >> 2) & 3, h = t & 3;
            const float* le = which ? le2 : le1;
            const float* ae = which ? ae2 : ae1;
            float s = 0.f;
            for (int c = 0; c < 32; c++)
                s += le[(h*32+c)*4 + j] * ae[h*32+c];
            g_M[which*16 + j*4 + h] = s;
        }
        return;
    }
    // ---- node1: two independent 128-thread halves ----
    __shared__ __align__(16) float sx[2][16*20];
    int tid = threadIdx.x;
    int sub = tid >> 7, stid = tid & 127;
    int n0 = (b - (B_HIST+B_CW+1))*32 + sub*16;
    float attS = asv[stid], attD = adv[stid], pbd = pb[stid];
    float wp[16], wl[16];
    #pragma unroll
    for (int q=0;q<4;q++){
        float4 a = *(const float4*)&pw[stid*16 + q*4];
        wp[q*4+0]=a.x; wp[q*4+1]=a.y; wp[q*4+2]=a.z; wp[q*4+3]=a.w;
        float4 bb = *(const float4*)&lw[stid*16 + q*4];
        wl[q*4+0]=bb.x; wl[q*4+1]=bb.y; wl[q*4+2]=bb.z; wl[q*4+3]=bb.w;
    }
    for (int i=stid;i<256;i+=128){
        int n=i>>4, k=i&15;
        int node=n0+n;
        sx[sub][n*20+k] = (node<NN) ? x[node*16+k] : 0.f;
    }
    __syncthreads();
    float acc0[16], acc1[16];
    #pragma unroll
    for (int n=0;n<16;n++){ acc0[n]=pbd; acc1[n]=0.f; }
    #pragma unroll
    for (int n=0;n<16;n++){
        float4 x0 = *(const float4*)&sx[sub][n*20];
        float4 x1 = *(const float4*)&sx[sub][n*20+4];
        float4 x2 = *(const float4*)&sx[sub][n*20+8];
        float4 x3 = *(const float4*)&sx[sub][n*20+12];
        float xv[16] = {x0.x,x0.y,x0.z,x0.w, x1.x,x1.y,x1.z,x1.w,
                        x2.x,x2.y,x2.z,x2.w, x3.x,x3.y,x3.z,x3.w};
        #pragma unroll
        for (int k=0;k<16;k++){
            acc0[n] = fmaf(xv[k], wp[k], acc0[n]);
            acc1[n] = fmaf(xv[k], wl[k], acc1[n]);
        }
    }
    int lane = stid&31, h = stid>>5;
    for (int n=0;n<16;n++){
        int node=n0+n;
        if (node>=NN) break;
        g_h0[node*128+stid]  = acc0[n];
        g_xsh[node*128+stid] = __float2half(acc1[n]);
        float s = acc1[n]*attS, dd = acc1[n]*attD;
        #pragma unroll
        for (int o=16;o>0;o>>=1){
            s  += __shfl_down_sync(0xffffffffu, s, o);
            dd += __shfl_down_sync(0xffffffffu, dd, o);
        }
        if (lane==0){ g_asrc[node*4+h]=s; g_adst[node*4+h]=dd; }
    }
}

// ---------------- scan: block sums + last-block scans partials ----------------
__global__ void __launch_bounds__(512) k_scanab(){
    __shared__ int sred[16];
    __shared__ int amlast;
    __shared__ int sb[128];
    int t = blockIdx.x*512 + threadIdx.x;
    int v = (t < NN) ? g_cnt[t] : 0;
    #pragma unroll
    for (int o=16;o>0;o>>=1) v += __shfl_xor_sync(0xffffffffu, v, o);
    int lane = threadIdx.x & 31, wid = threadIdx.x >> 5;
    if (lane == 0) sred[wid] = v;
    __syncthreads();
    if (threadIdx.x < 16){
        v = sred[threadIdx.x];
        #pragma unroll
        for (int o=8;o>0;o>>=1) v += __shfl_xor_sync(0xffffu, v, o);
    }
    if (threadIdx.x == 0){
        g_part[blockIdx.x] = v;
        __threadfence();
        int n = atomicAdd(&g_scancnt, 1);
        int last = (n == 97);
        if (last) g_scancnt = 0;      // restore zero-invariant
        amlast = last;
    }
    __syncthreads();
    if (amlast){
        __threadfence();
        int tt = threadIdx.x;
        int vv = 0;
        if (tt < 128){
            vv = (tt < 98) ? g_part[tt] : 0;
            sb[tt] = vv;
        }
        __syncthreads();
        for (int off=1; off<128; off<<=1){
            int u = (tt >= off && tt < 128) ? sb[tt-off] : 0;
            __syncthreads();
            if (tt < 128) sb[tt] += u;
            __syncthreads();
        }
        if (tt < 98) g_part[tt] = sb[tt] - vv;   // exclusive
    }
}

__global__ void __launch_bounds__(512) k_scanc(){
    __shared__ int s[512];
    int t = blockIdx.x*512 + threadIdx.x;
    int v = (t < NN) ? g_cnt[t] : 0;
    s[threadIdx.x] = v;
    __syncthreads();
    for (int off=1; off<512; off<<=1){
        int u = (threadIdx.x >= off) ? s[threadIdx.x-off] : 0;
        __syncthreads();
        s[threadIdx.x] += u;
        __syncthreads();
    }
    int excl = s[threadIdx.x] - v + g_part[blockIdx.x];
    if (t < NN){
        g_rowptr[t] = excl;
        g_cur[t]    = excl;
        g_cnt[t]    = 0;                // restore zero-invariant
        if (t == NN-1) g_rowptr[NN] = excl + v;
    }
}

// ---------------- edge encoder: 2 edges/thread packed into f32x2 lanes ----------------
#define QSTRIDE2 400000   // EE/2
__global__ void __launch_bounds__(256) k_edge(
        const float* __restrict__ ea, const int* __restrict__ ei,
        const float* __restrict__ w1, const float* __restrict__ b1,
        const float* __restrict__ w2, const float* __restrict__ b2){
    __shared__ __align__(16) unsigned long long sw1d[256];   // dup-packed w1
    __shared__ unsigned long long sb1d[32];                  // dup-packed b1
    __shared__ __align__(16) unsigned long long sWM1d[128];  // dup-packed [c][h]
    __shared__ __align__(16) unsigned long long sWM2d[128];
    __shared__ float sR0[8];
    int tid = threadIdx.x;
    if (tid < 256){ float v = w1[tid]; sw1d[tid] = packf2(v, v); }
    if (tid < 32){  float v = b1[tid]; sb1d[tid] = packf2(v, v); }
    if (tid < 128){
        int c = tid >> 2, h = tid & 3;
        float s1 = 0.f, s2 = 0.f;
        #pragma unroll
        for (int j=0;j<4;j++){
            float wv = w2[j*32+c];
            s1 = fmaf(wv, g_M[j*4+h],    s1);
            s2 = fmaf(wv, g_M[16+j*4+h], s2);
        }
        sWM1d[c*4+h] = packf2(s1, s1);
        sWM2d[c*4+h] = packf2(s2, s2);
    }
    if (tid >= 128 && tid < 136){
        int which = (tid-128) >> 2, h = tid & 3;
        float s = 0.f;
        #pragma unroll
        for (int j=0;j<4;j++) s = fmaf(b2[j], g_M[which*16+j*4+h], s);
        sR0[tid-128] = s;
    }
    __syncthreads();
    int gid = blockIdx.x*256 + tid;
    if (gid >= QSTRIDE2) return;
    int ee1 = gid + QSTRIDE2;
    float4 A0a = ((const float4*)ea)[gid*2];
    float4 A0b = ((const float4*)ea)[gid*2+1];
    float4 A1a = ((const float4*)ea)[ee1*2];
    float4 A1b = ((const float4*)ea)[ee1*2+1];
    unsigned long long av[8];
    av[0]=packf2(A0a.x,A1a.x); av[1]=packf2(A0a.y,A1a.y);
    av[2]=packf2(A0a.z,A1a.z); av[3]=packf2(A0a.w,A1a.w);
    av[4]=packf2(A0b.x,A1b.x); av[5]=packf2(A0b.y,A1b.y);
    av[6]=packf2(A0b.z,A1b.z); av[7]=packf2(A0b.w,A1b.w);
    unsigned long long r1p[4], r2p[4];
    #pragma unroll
    for (int k=0;k<4;k++){
        r1p[k] = pack2(sR0[k]);
        r2p[k] = pack2(sR0[4+k]);
    }
    #pragma unroll
    for (int c=0;c<32;c++){
        unsigned long long hv = sb1d[c];
        const ulonglong2* wr = (const ulonglong2*)&sw1d[c*8];
        ulonglong2 w01 = wr[0], w23 = wr[1], w45 = wr[2], w67 = wr[3];
        fma2(hv, w01.x, av[0]); fma2(hv, w01.y, av[1]);
        fma2(hv, w23.x, av[2]); fma2(hv, w23.y, av[3]);
        fma2(hv, w45.x, av[4]); fma2(hv, w45.y, av[5]);
        fma2(hv, w67.x, av[6]); fma2(hv, w67.y, av[7]);
        float h0 = fmaxf(lo2(hv), 0.f);
        float h1 = fmaxf(hi2(hv), 0.f);
        unsigned long long hp = packf2(h0, h1);
        const ulonglong2* m1 = (const ulonglong2*)&sWM1d[c*4];
        const ulonglong2* m2 = (const ulonglong2*)&sWM2d[c*4];
        ulonglong2 m1a = m1[0], m1b = m1[1];
        ulonglong2 m2a = m2[0], m2b = m2[1];
        fma2(r1p[0], m1a.x, hp); fma2(r1p[1], m1a.y, hp);
        fma2(r1p[2], m1b.x, hp); fma2(r1p[3], m1b.y, hp);
        fma2(r2p[0], m2a.x, hp); fma2(r2p[1], m2a.y, hp);
        fma2(r2p[2], m2b.x, hp); fma2(r2p[3], m2b.y, hp);
    }
    // edge 0 scatter
    {
        int srcn = ei[gid], d = ei[EE+gid];
        int pos = atomicAdd(&g_cur[d], 1);
        g_ssrc[pos] = srcn;
        float4 r1 = make_float4(lo2(r1p[0]), lo2(r1p[1]), lo2(r1p[2]), lo2(r1p[3]));
        float4 r2 = make_float4(lo2(r2p[0]), lo2(r2p[1]), lo2(r2p[2]), lo2(r2p[3]));
        ((float4*)g_sae1)[pos] = r1;
        ((float4*)g_sae2)[pos] = r2;
    }
    // edge 1 scatter
    {
        int srcn = ei[ee1], d = ei[EE+ee1];
        int pos = atomicAdd(&g_cur[d], 1);
        g_ssrc[pos] = srcn;
        float4 r1 = make_float4(hi2(r1p[0]), hi2(r1p[1]), hi2(r1p[2]), hi2(r1p[3]));
        float4 r2 = make_float4(hi2(r2p[0]), hi2(r2p[1]), hi2(r2p[2]), hi2(r2p[3]));
        ((float4*)g_sae1)[pos] = r1;
        ((float4*)g_sae2)[pos] = r2;
    }
}

// ---------------- fused GAT conv: 2 nodes/warp, HFMA2 gather + classifier ----------------
__global__ void __launch_bounds__(512) k_gat(const float* __restrict__ bias,
                      const float* __restrict__ gam,
                      const float* __restrict__ bet, int conv,
                      float* __restrict__ out){
    __shared__ float2 sp[16][2][68];   // [warp][half][h*17 + j]
    __shared__ float sCW[1920];
    __shared__ float sCB[5];
    int tid = threadIdx.x;
    if (conv){
        for (int i=tid;i<1920;i+=512) sCW[i] = g_CW[i];
        if (tid < 5) sCB[tid] = g_cb2[tid];
    }
    __syncthreads();
    int wid = tid >> 5, lane = tid & 31;
    int half = lane >> 4, sub = lane & 15;
    int node = blockIdx.x*32 + wid*2 + half;
    bool nv = node < NN;
    int h = sub >> 2;                      // head of this lane's 8 dims
    const float4* __restrict__ sae   = (const float4*)(conv ? g_sae2 : g_sae1);
    const float4* __restrict__ asrc4 = (const float4*)g_asrc;
    const char*   xbase = ((const char*)g_xsh) + sub*16;   // 8 halves per lane
    float4 ad = nv ? ((const float4*)g_adst)[node] : make_float4(0.f,0.f,0.f,0.f);
    int beg = nv ? g_rowptr[node]   : 0;
    int end = nv ? g_rowptr[node+1] : 0;
    int cnt = end - beg;
    int ocnt = __shfl_xor_sync(0xffffffffu, cnt, 16);
    int mx = cnt > ocnt ? cnt : ocnt;
    float4 den = make_float4(0.f,0.f,0.f,0.f);
    __half2 acc[4];
    acc[0]=acc[1]=acc[2]=acc[3]=__float2half2_rn(0.f);
    float2* myp = sp[wid][half];
    for (int b = 0; b < mx; b += 16){
        int j0 = b + sub;
        bool v = j0 < cnt;
        int cidx = v ? (beg + j0) : (end > beg ? end-1 : 0);
        int s = g_ssrc[cidx];
        float4 w = make_float4(0.f,0.f,0.f,0.f);
        if (v){
            float4 ae = sae[cidx];
            float4 as = asrc4[s];
            float ax = as.x+ad.x+ae.x; ax = ax>0.f?ax:0.2f*ax;
            float ay = as.y+ad.y+ae.y; ay = ay>0.f?ay:0.2f*ay;
            float az = as.z+ad.z+ae.z; az = az>0.f?az:0.2f*az;
            float aw = as.w+ad.w+ae.w; aw = aw>0.f?aw:0.2f*aw;
            w = make_float4(__expf(ax), __expf(ay), __expf(az), __expf(aw));
        }
        den.x += w.x; den.y += w.y; den.z += w.z; den.w += w.w;
        float so = __uint_as_float((unsigned)s * 256u);   // byte offset of fp16 row
        __syncwarp();
        myp[sub]      = make_float2(so, __uint_as_float(h2u(__float2half2_rn(w.x))));
        myp[17 + sub] = make_float2(so, __uint_as_float(h2u(__float2half2_rn(w.y))));
        myp[34 + sub] = make_float2(so, __uint_as_float(h2u(__float2half2_rn(w.z))));
        myp[51 + sub] = make_float2(so, __uint_as_float(h2u(__float2half2_rn(w.w))));
        __syncwarp();
        int jm = mx - b; if (jm > 16) jm = 16;
        const float2* hp2 = &myp[h*17];
        for (int c = 0; c < jm; c += 8){
            #pragma unroll
            for (int j = 0; j < 8; j++){
                float2 e2 = hp2[c+j];
                uint4 xr = *(const uint4*)(xbase + __float_as_uint(e2.x));
                unsigned wb = __float_as_uint(e2.y);
                __half2 wh = *reinterpret_cast<__half2*>(&wb);
                acc[0] = __hfma2(*reinterpret_cast<__half2*>(&xr.x), wh, acc[0]);
                acc[1] = __hfma2(*reinterpret_cast<__half2*>(&xr.y), wh, acc[1]);
                acc[2] = __hfma2(*reinterpret_cast<__half2*>(&xr.z), wh, acc[2]);
                acc[3] = __hfma2(*reinterpret_cast<__half2*>(&xr.w), wh, acc[3]);
            }
        }
    }
    // den reduce within half-warp (offsets < 16 keep halves separate)
    #pragma unroll
    for (int o=8;o>0;o>>=1){
        den.x += __shfl_xor_sync(0xffffffffu, den.x, o);
        den.y += __shfl_xor_sync(0xffffffffu, den.y, o);
        den.z += __shfl_xor_sync(0xffffffffu, den.z, o);
        den.w += __shfl_xor_sync(0xffffffffu, den.w, o);
    }
    float dh = (h==0)?den.x:(h==1)?den.y:(h==2)?den.z:den.w;
    float inv = 1.f/(dh + 1e-16f);
    const float* hp = conv ? g_h1 : g_h0;
    float*       ho = conv ? g_h2 : g_h1;
    float4 hva = nv ? *(const float4*)&hp[node*128 + sub*8]     : make_float4(0.f,0.f,0.f,0.f);
    float4 hvb = nv ? *(const float4*)&hp[node*128 + sub*8 + 4] : make_float4(0.f,0.f,0.f,0.f);
    float4 bva = *(const float4*)&bias[sub*8];
    float4 bvb = *(const float4*)&bias[sub*8+4];
    float2 f0 = __half22float2(acc[0]);
    float2 f1 = __half22float2(acc[1]);
    float2 f2 = __half22float2(acc[2]);
    float2 f3 = __half22float2(acc[3]);
    float fa[8] = {f0.x,f0.y,f1.x,f1.y,f2.x,f2.y,f3.x,f3.y};
    float hvv[8] = {hva.x,hva.y,hva.z,hva.w,hvb.x,hvb.y,hvb.z,hvb.w};
    float bvv[8] = {bva.x,bva.y,bva.z,bva.w,bvb.x,bvb.y,bvb.z,bvb.w};
    float ra[8];
    float s1 = 0.f, s2 = 0.f;
    #pragma unroll
    for (int i=0;i<8;i++){
        float r = fa[i]*inv + bvv[i];
        r = (r>0.f) ? r : (__expf(r)-1.f);
        r += hvv[i];
        ra[i] = r;
        s1 += r; s2 += r*r;
    }
    #pragma unroll
    for (int o=8;o>0;o>>=1){
        s1 += __shfl_xor_sync(0xffffffffu, s1, o);
        s2 += __shfl_xor_sync(0xffffffffu, s2, o);
    }
    float mu  = s1 * (1.f/128.f);
    float var = s2 * (1.f/128.f) - mu*mu;
    float rs  = rsqrtf(var + 1e-5f);
    float4 gva = *(const float4*)&gam[sub*8];
    float4 gvb = *(const float4*)&gam[sub*8+4];
    float4 bea = *(const float4*)&bet[sub*8];
    float4 beb = *(const float4*)&bet[sub*8+4];
    float gvv[8] = {gva.x,gva.y,gva.z,gva.w,gvb.x,gvb.y,gvb.z,gvb.w};
    float bev[8] = {bea.x,bea.y,bea.z,bea.w,beb.x,beb.y,beb.z,beb.w};
    float ov[8];
    #pragma unroll
    for (int i=0;i<8;i++) ov[i] = (ra[i]-mu)*rs*gvv[i] + bev[i];
    if (nv){
        float4 oa = make_float4(ov[0],ov[1],ov[2],ov[3]);
        float4 ob = make_float4(ov[4],ov[5],ov[6],ov[7]);
        *(float4*)&ho[node*128 + sub*8]     = oa;
        *(float4*)&ho[node*128 + sub*8 + 4] = ob;
    }
    if (conv){
        float4 a0a = nv ? *(const float4*)&g_h0[node*128 + sub*8]     : make_float4(0.f,0.f,0.f,0.f);
        float4 a0b = nv ? *(const float4*)&g_h0[node*128 + sub*8 + 4] : make_float4(0.f,0.f,0.f,0.f);
        float a0[8] = {a0a.x,a0a.y,a0a.z,a0a.w,a0b.x,a0b.y,a0b.z,a0b.w};
        float lg[5];
        #pragma unroll
        for (int c=0;c<5;c++){
            const float* w = &sCW[c*384];
            float4 b0a = *(const float4*)&w[sub*8];
            float4 b0b = *(const float4*)&w[sub*8+4];
            float4 b1a = *(const float4*)&w[128 + sub*8];
            float4 b1b = *(const float4*)&w[128 + sub*8+4];
            float4 b2a = *(const float4*)&w[256 + sub*8];
            float4 b2b = *(const float4*)&w[256 + sub*8+4];
            float w0[8] = {b0a.x,b0a.y,b0a.z,b0a.w,b0b.x,b0b.y,b0b.z,b0b.w};
            float w1[8] = {b1a.x,b1a.y,b1a.z,b1a.w,b1b.x,b1b.y,b1b.z,b1b.w};
            float w2[8] = {b2a.x,b2a.y,b2a.z,b2a.w,b2b.x,b2b.y,b2b.z,b2b.w};
            float p = 0.f;
            #pragma unroll
            for (int i=0;i<8;i++){
                p = fmaf(a0[i],  w0[i], p);
                p = fmaf(hvv[i], w1[i], p);
                p = fmaf(ov[i],  w2[i], p);
            }
            #pragma unroll
            for (int o=8;o>0;o>>=1) p += __shfl_xor_sync(0xffffffffu, p, o);
            lg[c] = p + sCB[c];
        }
        if (sub == 0 && nv){
            float m = lg[0];
            #pragma unroll
            for (int c=1;c<5;c++) m = fmaxf(m, lg[c]);
            float s = 0.f;
            #pragma unroll
            for (int c=0;c<5;c++) s += __expf(lg[c]-m);
            float ls = logf(s);
            #pragma unroll
            for (int c=0;c<5;c++) out[node*5+c] = lg[c]-m-ls;
        }
    }
}

// ---------------- conv2 GEMM + fused attention dots (fp16 xs output) ----------------
__global__ void __launch_bounds__(256) k_node2(const float* __restrict__ lin,
                                               const float* __restrict__ asv,
                                               const float* __restrict__ adv){
    __shared__ float sA[16*132];
    __shared__ float sB[16*132];
    int tid = threadIdx.x;
    int tx = tid & 15, ty = tid >> 4;
    int n0 = blockIdx.x*128;
    unsigned long long acc[8][4];
    #pragma unroll
    for (int r=0;r<8;r++)
        #pragma unroll
        for (int p=0;p<4;p++) acc[r][p] = 0ULL;
    for (int kc=0;kc<8;kc++){
        __syncthreads();
        #pragma unroll
        for (int t=tid;t<512;t+=256){
            int r = t>>2, q = t&3;
            int node = n0 + r;
            float4 v = (node<NN) ? *(const float4*)&g_h1[node*128 + kc*16 + q*4]
                                 : make_float4(0.f,0.f,0.f,0.f);
            sA[(q*4+0)*132+r]=v.x; sA[(q*4+1)*132+r]=v.y;
            sA[(q*4+2)*132+r]=v.z; sA[(q*4+3)*132+r]=v.w;
        }
        #pragma unroll
        for (int t=tid;t<512;t+=256){
            int d = t>>2, q = t&3;
            float4 v = *(const float4*)&lin[d*128 + kc*16 + q*4];
            sB[(q*4+0)*132+d]=v.x; sB[(q*4+1)*132+d]=v.y;
            sB[(q*4+2)*132+d]=v.z; sB[(q*4+3)*132+d]=v.w;
        }
        __syncthreads();
        #pragma unroll
        for (int k=0;k<16;k++){
            float4 a0 = *(const float4*)&sA[k*132 + ty*8];
            float4 a1 = *(const float4*)&sA[k*132 + ty*8 + 4];
            ulonglong2 b0 = *(const ulonglong2*)&sB[k*132 + tx*8];
            ulonglong2 b1 = *(const ulonglong2*)&sB[k*132 + tx*8 + 4];
            unsigned long long bp0=b0.x, bp1=b0.y, bp2=b1.x, bp3=b1.y;
            float ar[8] = {a0.x,a0.y,a0.z,a0.w,a1.x,a1.y,a1.z,a1.w};
            #pragma unroll
            for (int r=0;r<8;r++){
                unsigned long long a2 = pack2(ar[r]);
                fma2(acc[r][0], a2, bp0);
                fma2(acc[r][1], a2, bp1);
                fma2(acc[r][2], a2, bp2);
                fma2(acc[r][3], a2, bp3);
            }
        }
    }
    float4 ws0 = *(const float4*)&asv[tx*8];
    float4 ws1 = *(const float4*)&asv[tx*8+4];
    float4 wd0 = *(const float4*)&adv[tx*8];
    float4 wd1 = *(const float4*)&adv[tx*8+4];
    int hh = tx >> 2;
    #pragma unroll
    for (int r=0;r<8;r++){
        int node = n0 + ty*8 + r;
        if (node < NN){
            float f0=lo2(acc[r][0]), f1=hi2(acc[r][0]);
            float f2=lo2(acc[r][1]), f3=hi2(acc[r][1]);
            float f4=lo2(acc[r][2]), f5=hi2(acc[r][2]);
            float f6=lo2(acc[r][3]), f7=hi2(acc[r][3]);
            uint4 st;
            st.x = h2u(__floats2half2_rn(f0, f1));
            st.y = h2u(__floats2half2_rn(f2, f3));
            st.z = h2u(__floats2half2_rn(f4, f5));
            st.w = h2u(__floats2half2_rn(f6, f7));
            *(uint4*)(((char*)g_xsh) + node*256 + tx*16) = st;
            float s = f0*ws0.x + f1*ws0.y + f2*ws0.z + f3*ws0.w
                    + f4*ws1.x + f5*ws1.y + f6*ws1.z + f7*ws1.w;
            float d = f0*wd0.x + f1*wd0.y + f2*wd0.z + f3*wd0.w
                    + f4*wd1.x + f5*wd1.y + f6*wd1.z + f7*wd1.w;
            s += __shfl_xor_sync(0xffffffffu, s, 1);
            s += __shfl_xor_sync(0xffffffffu, s, 2);
            d += __shfl_xor_sync(0xffffffffu, d, 1);
            d += __shfl_xor_sync(0xffffffffu, d, 2);
            if ((tx & 3) == 0){
                g_asrc[node*4+hh] = s;
                g_adst[node*4+hh] = d;
            }
        }
    }
}

// ---------------- launcher ----------------
extern "C" void kernel_launch(void* const* d_in, const int* in_sizes, int n_in,
                              void* d_out, int out_size){
    const float* x      = (const float*)d_in[0];
    const int*   ei     = (const int*)  d_in[1];
    const float* ea     = (const float*)d_in[2];
    const float* ee_w1  = (const float*)d_in[3];
    const float* ee_b1  = (const float*)d_in[4];
    const float* ee_w2  = (const float*)d_in[5];
    const float* ee_b2  = (const float*)d_in[6];
    const float* proj_w = (const float*)d_in[7];
    const float* proj_b = (const float*)d_in[8];
    const float* c1_lin = (const float*)d_in[9];
    const float* c1_as  = (const float*)d_in[10];
    const float* c1_ad  = (const float*)d_in[11];
    const float* c1_le  = (const float*)d_in[12];
    const float* c1_ae  = (const float*)d_in[13];
    const float* c1_b   = (const float*)d_in[14];
    const float* c2_lin = (const float*)d_in[15];
    const float* c2_as  = (const float*)d_in[16];
    const float* c2_ad  = (const float*)d_in[17];
    const float* c2_le  = (const float*)d_in[18];
    const float* c2_ae  = (const float*)d_in[19];
    const float* c2_b   = (const float*)d_in[20];
    const float* n1_g   = (const float*)d_in[21];
    const float* n1_b   = (const float*)d_in[22];
    const float* n2_g   = (const float*)d_in[23];
    const float* n2_b   = (const float*)d_in[24];
    const float* jk_w   = (const float*)d_in[25];
    const float* jk_b   = (const float*)d_in[26];
    const float* cls_w  = (const float*)d_in[27];
    const float* cls_b  = (const float*)d_in[28];
    float* out = (float*)d_out;

    k_fused1<<<B_HIST+B_CW+1+B_NODE1,256>>>(ei, c1_le, c1_ae, c2_le, c2_ae,
                                            cls_w, cls_b, jk_w, jk_b,
                                            x, proj_w, proj_b, c1_lin, c1_as, c1_ad);
    k_scanab<<<98,512>>>();
    k_scanc<<<98,512>>>();
    k_edge<<<(QSTRIDE2+255)/256,256>>>(ea, ei, ee_w1, ee_b1, ee_w2, ee_b2);
    k_gat<<<(NN+31)/32,512>>>(c1_b, n1_g, n1_b, 0, out);
    k_node2<<<(NN+127)/128,256>>>(c2_lin, c2_as, c2_ad);
    k_gat<<<(NN+31)/32,512>>>(c2_b, n2_g, n2_b, 1, out);
}

// round 16
// speedup vs baseline: 1.0267x; 1.0267x over previous
#include <cuda_runtime.h>
#include <cuda_fp16.h>
#include <math.h>

#define NN 50000
#define EE 800000

// ---------------- scratch (device globals; zero-initialized at load) ----------------
__device__ float  g_sae1[EE*4];   // a_edge (conv1) in CSR order
__device__ float  g_sae2[EE*4];   // a_edge (conv2) in CSR order
__device__ int    g_ssrc[EE];     // src node in CSR order
__device__ int    g_cnt[NN];      // invariant: zero at entry (scanc re-zeroes)
__device__ int    g_cur[NN];
__device__ int    g_rowptr[NN+1];
__device__ int    g_part[128];
__device__ int    g_scancnt;      // invariant: zero at entry (last block re-zeroes)
__device__ float  g_h0[NN*128];
__device__ float  g_h1[NN*128];
__device__ float  g_h2[NN*128];
__device__ __half g_xsh[NN*128];  // fp16 transformed features (gather source)
__device__ float  g_asrc[NN*4];
__device__ float  g_adst[NN*4];
__device__ float  g_M[32];        // [conv*16 + j*4 + h]
__device__ float  g_CW[5*384];    // collapsed classifier: cls_w @ jk_w
__device__ float  g_cb2[5];       // collapsed bias

// ---------------- helpers ----------------
__device__ __forceinline__ unsigned long long pack2(float x){
    unsigned long long r;
    unsigned int u = __float_as_uint(x);
    asm("mov.b64 %0, {%1, %1};" : "=l"(r) : "r"(u));
    return r;
}
__device__ __forceinline__ void fma2(unsigned long long& acc,
                                     unsigned long long a, unsigned long long b){
    asm("fma.rn.f32x2 %0, %1, %2, %0;" : "+l"(acc) : "l"(a), "l"(b));
}
__device__ __forceinline__ float lo2(unsigned long long v){
    unsigned int a, b;
    asm("mov.b64 {%0, %1}, %2;" : "=r"(a), "=r"(b) : "l"(v));
    return __uint_as_float(a);
}
__device__ __forceinline__ float hi2(unsigned long long v){
    unsigned int a, b;
    asm("mov.b64 {%0, %1}, %2;" : "=r"(a), "=r"(b) : "l"(v));
    return __uint_as_float(b);
}
__device__ __forceinline__ unsigned h2u(__half2 h){
    return *reinterpret_cast<unsigned*>(&h);
}
__device__ __forceinline__ __half2 u2h(unsigned u){
    return *reinterpret_cast<__half2*>(&u);
}

// ============ launch 1: hist + CW-prep + M-prep + node1, fused ============
#define B_HIST 782
#define B_CW   241
#define B_NODE1 1563

__global__ void __launch_bounds__(256) k_fused1(
        const int* __restrict__ ei,
        const float* __restrict__ le1, const float* __restrict__ ae1,
        const float* __restrict__ le2, const float* __restrict__ ae2,
        const float* __restrict__ cw,  const float* __restrict__ cb,
        const float* __restrict__ jkw, const float* __restrict__ jkb,
        const float* __restrict__ x,
        const float* __restrict__ pw, const float* __restrict__ pb,
        const float* __restrict__ lw,
        const float* __restrict__ asv, const float* __restrict__ adv){
    int b = blockIdx.x;
    if (b < B_HIST){
        int t = b*256 + threadIdx.x;
        if (t < EE/4){
            int4 d4 = ((const int4*)(ei+EE))[t];
            atomicAdd(&g_cnt[d4.x], 1);
            atomicAdd(&g_cnt[d4.y], 1);
            atomicAdd(&g_cnt[d4.z], 1);
            atomicAdd(&g_cnt[d4.w], 1);
        }
        return;
    }
    if (b < B_HIST + B_CW){
        int w = (b-B_HIST)*8 + (threadIdx.x >> 5);
        int lane = threadIdx.x & 31;
        if (w >= 5*385) return;
        int c = w / 385, j = w % 385;
        float4 a = *(const float4*)&cw[c*128 + lane*4];
        int d = lane*4;
        float s;
        if (j < 384){
            s = a.x*jkw[(d+0)*384+j] + a.y*jkw[(d+1)*384+j]
              + a.z*jkw[(d+2)*384+j] + a.w*jkw[(d+3)*384+j];
        } else {
            float4 bb = *(const float4*)&jkb[d];
            s = a.x*bb.x + a.y*bb.y + a.z*bb.z + a.w*bb.w;
        }
        #pragma unroll
        for (int o=16;o>0;o>>=1) s += __shfl_xor_sync(0xffffffffu, s, o);
        if (lane == 0){
            if (j < 384) g_CW[c*384+j] = s;
            else         g_cb2[c] = s + cb[c];
        }
        return;
    }
    if (b == B_HIST + B_CW){
        int t = threadIdx.x;
        if (t < 32){
            int which = t >> 4, j = (t >> 2) & 3, h = t & 3;
            const float* le = which ? le2 : le1;
            const float* ae = which ? ae2 : ae1;
            float s = 0.f;
            for (int c = 0; c < 32; c++)
                s += le[(h*32+c)*4 + j] * ae[h*32+c];
            g_M[which*16 + j*4 + h] = s;
        }
        return;
    }
    // ---- node1: two independent 128-thread halves ----
    __shared__ __align__(16) float sx[2][16*20];
    int tid = threadIdx.x;
    int sub = tid >> 7, stid = tid & 127;
    int n0 = (b - (B_HIST+B_CW+1))*32 + sub*16;
    float attS = asv[stid], attD = adv[stid], pbd = pb[stid];
    float wp[16], wl[16];
    #pragma unroll
    for (int q=0;q<4;q++){
        float4 a = *(const float4*)&pw[stid*16 + q*4];
        wp[q*4+0]=a.x; wp[q*4+1]=a.y; wp[q*4+2]=a.z; wp[q*4+3]=a.w;
        float4 bb = *(const float4*)&lw[stid*16 + q*4];
        wl[q*4+0]=bb.x; wl[q*4+1]=bb.y; wl[q*4+2]=bb.z; wl[q*4+3]=bb.w;
    }
    for (int i=stid;i<256;i+=128){
        int n=i>>4, k=i&15;
        int node=n0+n;
        sx[sub][n*20+k] = (node<NN) ? x[node*16+k] : 0.f;
    }
    __syncthreads();
    float acc0[16], acc1[16];
    #pragma unroll
    for (int n=0;n<16;n++){ acc0[n]=pbd; acc1[n]=0.f; }
    #pragma unroll
    for (int n=0;n<16;n++){
        float4 x0 = *(const float4*)&sx[sub][n*20];
        float4 x1 = *(const float4*)&sx[sub][n*20+4];
        float4 x2 = *(const float4*)&sx[sub][n*20+8];
        float4 x3 = *(const float4*)&sx[sub][n*20+12];
        float xv[16] = {x0.x,x0.y,x0.z,x0.w, x1.x,x1.y,x1.z,x1.w,
                        x2.x,x2.y,x2.z,x2.w, x3.x,x3.y,x3.z,x3.w};
        #pragma unroll
        for (int k=0;k<16;k++){
            acc0[n] = fmaf(xv[k], wp[k], acc0[n]);
            acc1[n] = fmaf(xv[k], wl[k], acc1[n]);
        }
    }
    int lane = stid&31, h = stid>>5;
    for (int n=0;n<16;n++){
        int node=n0+n;
        if (node>=NN) break;
        g_h0[node*128+stid]  = acc0[n];
        g_xsh[node*128+stid] = __float2half(acc1[n]);
        float s = acc1[n]*attS, dd = acc1[n]*attD;
        #pragma unroll
        for (int o=16;o>0;o>>=1){
            s  += __shfl_down_sync(0xffffffffu, s, o);
            dd += __shfl_down_sync(0xffffffffu, dd, o);
        }
        if (lane==0){ g_asrc[node*4+h]=s; g_adst[node*4+h]=dd; }
    }
}

// ---------------- scan: block sums + last-block scans partials ----------------
__global__ void __launch_bounds__(512) k_scanab(){
    __shared__ int sred[16];
    __shared__ int amlast;
    __shared__ int sb[128];
    int t = blockIdx.x*512 + threadIdx.x;
    int v = (t < NN) ? g_cnt[t] : 0;
    #pragma unroll
    for (int o=16;o>0;o>>=1) v += __shfl_xor_sync(0xffffffffu, v, o);
    int lane = threadIdx.x & 31, wid = threadIdx.x >> 5;
    if (lane == 0) sred[wid] = v;
    __syncthreads();
    if (threadIdx.x < 16){
        v = sred[threadIdx.x];
        #pragma unroll
        for (int o=8;o>0;o>>=1) v += __shfl_xor_sync(0xffffu, v, o);
    }
    if (threadIdx.x == 0){
        g_part[blockIdx.x] = v;
        __threadfence();
        int n = atomicAdd(&g_scancnt, 1);
        int last = (n == 97);
        if (last) g_scancnt = 0;      // restore zero-invariant
        amlast = last;
    }
    __syncthreads();
    if (amlast){
        __threadfence();
        int tt = threadIdx.x;
        int vv = 0;
        if (tt < 128){
            vv = (tt < 98) ? g_part[tt] : 0;
            sb[tt] = vv;
        }
        __syncthreads();
        for (int off=1; off<128; off<<=1){
            int u = (tt >= off && tt < 128) ? sb[tt-off] : 0;
            __syncthreads();
            if (tt < 128) sb[tt] += u;
            __syncthreads();
        }
        if (tt < 98) g_part[tt] = sb[tt] - vv;   // exclusive
    }
}

__global__ void __launch_bounds__(512) k_scanc(){
    __shared__ int s[512];
    int t = blockIdx.x*512 + threadIdx.x;
    int v = (t < NN) ? g_cnt[t] : 0;
    s[threadIdx.x] = v;
    __syncthreads();
    for (int off=1; off<512; off<<=1){
        int u = (threadIdx.x >= off) ? s[threadIdx.x-off] : 0;
        __syncthreads();
        s[threadIdx.x] += u;
        __syncthreads();
    }
    int excl = s[threadIdx.x] - v + g_part[blockIdx.x];
    if (t < NN){
        g_rowptr[t] = excl;
        g_cur[t]    = excl;
        g_cnt[t]    = 0;                // restore zero-invariant
        if (t == NN-1) g_rowptr[NN] = excl + v;
    }
}

// ---------------- edge encoder: 2 edges/thread in half2 lanes (HFMA2) ----------------
#define QSTRIDE2 400000   // EE/2
__global__ void __launch_bounds__(256) k_edge(
        const float* __restrict__ ea, const int* __restrict__ ei,
        const float* __restrict__ w1, const float* __restrict__ b1,
        const float* __restrict__ w2, const float* __restrict__ b2){
    __shared__ __align__(16) unsigned sw1h[256];   // dup half2(w1)
    __shared__ unsigned sb1h[32];                  // dup half2(b1)
    __shared__ __align__(16) unsigned sWM1h[128];  // dup half2 [c][h]
    __shared__ __align__(16) unsigned sWM2h[128];
    __shared__ float sR0[8];
    int tid = threadIdx.x;
    if (tid < 256) sw1h[tid] = h2u(__float2half2_rn(w1[tid]));
    if (tid < 32)  sb1h[tid] = h2u(__float2half2_rn(b1[tid]));
    if (tid < 128){
        int c = tid >> 2, h = tid & 3;
        float s1 = 0.f, s2 = 0.f;
        #pragma unroll
        for (int j=0;j<4;j++){
            float wv = w2[j*32+c];
            s1 = fmaf(wv, g_M[j*4+h],    s1);
            s2 = fmaf(wv, g_M[16+j*4+h], s2);
        }
        sWM1h[c*4+h] = h2u(__float2half2_rn(s1));
        sWM2h[c*4+h] = h2u(__float2half2_rn(s2));
    }
    if (tid >= 128 && tid < 136){
        int which = (tid-128) >> 2, h = tid & 3;
        float s = 0.f;
        #pragma unroll
        for (int j=0;j<4;j++) s = fmaf(b2[j], g_M[which*16+j*4+h], s);
        sR0[tid-128] = s;
    }
    __syncthreads();
    int gid = blockIdx.x*256 + tid;
    if (gid >= QSTRIDE2) return;
    int ee1 = gid + QSTRIDE2;
    float4 A0a = ((const float4*)ea)[gid*2];
    float4 A0b = ((const float4*)ea)[gid*2+1];
    float4 A1a = ((const float4*)ea)[ee1*2];
    float4 A1b = ((const float4*)ea)[ee1*2+1];
    __half2 av[8];
    av[0] = __floats2half2_rn(A0a.x, A1a.x);
    av[1] = __floats2half2_rn(A0a.y, A1a.y);
    av[2] = __floats2half2_rn(A0a.z, A1a.z);
    av[3] = __floats2half2_rn(A0a.w, A1a.w);
    av[4] = __floats2half2_rn(A0b.x, A1b.x);
    av[5] = __floats2half2_rn(A0b.y, A1b.y);
    av[6] = __floats2half2_rn(A0b.z, A1b.z);
    av[7] = __floats2half2_rn(A0b.w, A1b.w);
    __half2 r1h[4], r2h[4];
    #pragma unroll
    for (int k=0;k<4;k++){
        r1h[k] = __float2half2_rn(sR0[k]);
        r2h[k] = __float2half2_rn(sR0[4+k]);
    }
    const __half2 zero2 = __float2half2_rn(0.f);
    #pragma unroll
    for (int c=0;c<32;c++){
        uint4 wv0 = *(const uint4*)&sw1h[c*8];
        uint4 wv1 = *(const uint4*)&sw1h[c*8+4];
        __half2 hv = u2h(sb1h[c]);
        hv = __hfma2(u2h(wv0.x), av[0], hv);
        hv = __hfma2(u2h(wv0.y), av[1], hv);
        hv = __hfma2(u2h(wv0.z), av[2], hv);
        hv = __hfma2(u2h(wv0.w), av[3], hv);
        hv = __hfma2(u2h(wv1.x), av[4], hv);
        hv = __hfma2(u2h(wv1.y), av[5], hv);
        hv = __hfma2(u2h(wv1.z), av[6], hv);
        hv = __hfma2(u2h(wv1.w), av[7], hv);
        hv = __hmax2(hv, zero2);
        uint4 m1 = *(const uint4*)&sWM1h[c*4];
        uint4 m2 = *(const uint4*)&sWM2h[c*4];
        r1h[0] = __hfma2(u2h(m1.x), hv, r1h[0]);
        r1h[1] = __hfma2(u2h(m1.y), hv, r1h[1]);
        r1h[2] = __hfma2(u2h(m1.z), hv, r1h[2]);
        r1h[3] = __hfma2(u2h(m1.w), hv, r1h[3]);
        r2h[0] = __hfma2(u2h(m2.x), hv, r2h[0]);
        r2h[1] = __hfma2(u2h(m2.y), hv, r2h[1]);
        r2h[2] = __hfma2(u2h(m2.z), hv, r2h[2]);
        r2h[3] = __hfma2(u2h(m2.w), hv, r2h[3]);
    }
    // edge 0 scatter (low halves)
    {
        int srcn = ei[gid], d = ei[EE+gid];
        int pos = atomicAdd(&g_cur[d], 1);
        g_ssrc[pos] = srcn;
        float4 r1 = make_float4(__low2float(r1h[0]), __low2float(r1h[1]),
                                __low2float(r1h[2]), __low2float(r1h[3]));
        float4 r2 = make_float4(__low2float(r2h[0]), __low2float(r2h[1]),
                                __low2float(r2h[2]), __low2float(r2h[3]));
        ((float4*)g_sae1)[pos] = r1;
        ((float4*)g_sae2)[pos] = r2;
    }
    // edge 1 scatter (high halves)
    {
        int srcn = ei[ee1], d = ei[EE+ee1];
        int pos = atomicAdd(&g_cur[d], 1);
        g_ssrc[pos] = srcn;
        float4 r1 = make_float4(__high2float(r1h[0]), __high2float(r1h[1]),
                                __high2float(r1h[2]), __high2float(r1h[3]));
        float4 r2 = make_float4(__high2float(r2h[0]), __high2float(r2h[1]),
                                __high2float(r2h[2]), __high2float(r2h[3]));
        ((float4*)g_sae1)[pos] = r1;
        ((float4*)g_sae2)[pos] = r2;
    }
}

// ---------------- fused GAT conv: 2 nodes/warp, HFMA2 gather + classifier ----------------
__global__ void __launch_bounds__(512) k_gat(const float* __restrict__ bias,
                      const float* __restrict__ gam,
                      const float* __restrict__ bet, int conv,
                      float* __restrict__ out){
    __shared__ float2 sp[16][2][68];   // [warp][half][h*17 + j]
    __shared__ float sCW[1920];
    __shared__ float sCB[5];
    int tid = threadIdx.x;
    if (conv){
        for (int i=tid;i<1920;i+=512) sCW[i] = g_CW[i];
        if (tid < 5) sCB[tid] = g_cb2[tid];
    }
    __syncthreads();
    int wid = tid >> 5, lane = tid & 31;
    int half = lane >> 4, sub = lane & 15;
    int node = blockIdx.x*32 + wid*2 + half;
    bool nv = node < NN;
    int h = sub >> 2;                      // head of this lane's 8 dims
    const float4* __restrict__ sae   = (const float4*)(conv ? g_sae2 : g_sae1);
    const float4* __restrict__ asrc4 = (const float4*)g_asrc;
    const char*   xbase = ((const char*)g_xsh) + sub*16;   // 8 halves per lane
    float4 ad = nv ? ((const float4*)g_adst)[node] : make_float4(0.f,0.f,0.f,0.f);
    int beg = nv ? g_rowptr[node]   : 0;
    int end = nv ? g_rowptr[node+1] : 0;
    int cnt = end - beg;
    int ocnt = __shfl_xor_sync(0xffffffffu, cnt, 16);
    int mx = cnt > ocnt ? cnt : ocnt;
    float4 den = make_float4(0.f,0.f,0.f,0.f);
    __half2 acc[4];
    acc[0]=acc[1]=acc[2]=acc[3]=__float2half2_rn(0.f);
    float2* myp = sp[wid][half];
    for (int b = 0; b < mx; b += 16){
        int j0 = b + sub;
        bool v = j0 < cnt;
        int cidx = v ? (beg + j0) : (end > beg ? end-1 : 0);
        int s = g_ssrc[cidx];
        float4 w = make_float4(0.f,0.f,0.f,0.f);
        if (v){
            float4 ae = sae[cidx];
            float4 as = asrc4[s];
            float ax = as.x+ad.x+ae.x; ax = ax>0.f?ax:0.2f*ax;
            float ay = as.y+ad.y+ae.y; ay = ay>0.f?ay:0.2f*ay;
            float az = as.z+ad.z+ae.z; az = az>0.f?az:0.2f*az;
            float aw = as.w+ad.w+ae.w; aw = aw>0.f?aw:0.2f*aw;
            w = make_float4(__expf(ax), __expf(ay), __expf(az), __expf(aw));
        }
        den.x += w.x; den.y += w.y; den.z += w.z; den.w += w.w;
        float so = __uint_as_float((unsigned)s * 256u);   // byte offset of fp16 row
        __syncwarp();
        myp[sub]      = make_float2(so, __uint_as_float(h2u(__float2half2_rn(w.x))));
        myp[17 + sub] = make_float2(so, __uint_as_float(h2u(__float2half2_rn(w.y))));
        myp[34 + sub] = make_float2(so, __uint_as_float(h2u(__float2half2_rn(w.z))));
        myp[51 + sub] = make_float2(so, __uint_as_float(h2u(__float2half2_rn(w.w))));
        __syncwarp();
        int jm = mx - b; if (jm > 16) jm = 16;
        const float2* hp2 = &myp[h*17];
        for (int c = 0; c < jm; c += 8){
            #pragma unroll
            for (int j = 0; j < 8; j++){
                float2 e2 = hp2[c+j];
                uint4 xr = *(const uint4*)(xbase + __float_as_uint(e2.x));
                unsigned wb = __float_as_uint(e2.y);
                __half2 wh = *reinterpret_cast<__half2*>(&wb);
                acc[0] = __hfma2(*reinterpret_cast<__half2*>(&xr.x), wh, acc[0]);
                acc[1] = __hfma2(*reinterpret_cast<__half2*>(&xr.y), wh, acc[1]);
                acc[2] = __hfma2(*reinterpret_cast<__half2*>(&xr.z), wh, acc[2]);
                acc[3] = __hfma2(*reinterpret_cast<__half2*>(&xr.w), wh, acc[3]);
            }
        }
    }
    // den reduce within half-warp (offsets < 16 keep halves separate)
    #pragma unroll
    for (int o=8;o>0;o>>=1){
        den.x += __shfl_xor_sync(0xffffffffu, den.x, o);
        den.y += __shfl_xor_sync(0xffffffffu, den.y, o);
        den.z += __shfl_xor_sync(0xffffffffu, den.z, o);
        den.w += __shfl_xor_sync(0xffffffffu, den.w, o);
    }
    float dh = (h==0)?den.x:(h==1)?den.y:(h==2)?den.z:den.w;
    float inv = 1.f/(dh + 1e-16f);
    const float* hp = conv ? g_h1 : g_h0;
    float*       ho = conv ? g_h2 : g_h1;
    float4 hva = nv ? *(const float4*)&hp[node*128 + sub*8]     : make_float4(0.f,0.f,0.f,0.f);
    float4 hvb = nv ? *(const float4*)&hp[node*128 + sub*8 + 4] : make_float4(0.f,0.f,0.f,0.f);
    float4 bva = *(const float4*)&bias[sub*8];
    float4 bvb = *(const float4*)&bias[sub*8+4];
    float2 f0 = __half22float2(acc[0]);
    float2 f1 = __half22float2(acc[1]);
    float2 f2 = __half22float2(acc[2]);
    float2 f3 = __half22float2(acc[3]);
    float fa[8] = {f0.x,f0.y,f1.x,f1.y,f2.x,f2.y,f3.x,f3.y};
    float hvv[8] = {hva.x,hva.y,hva.z,hva.w,hvb.x,hvb.y,hvb.z,hvb.w};
    float bvv[8] = {bva.x,bva.y,bva.z,bva.w,bvb.x,bvb.y,bvb.z,bvb.w};
    float ra[8];
    float s1 = 0.f, s2 = 0.f;
    #pragma unroll
    for (int i=0;i<8;i++){
        float r = fa[i]*inv + bvv[i];
        r = (r>0.f) ? r : (__expf(r)-1.f);
        r += hvv[i];
        ra[i] = r;
        s1 += r; s2 += r*r;
    }
    #pragma unroll
    for (int o=8;o>0;o>>=1){
        s1 += __shfl_xor_sync(0xffffffffu, s1, o);
        s2 += __shfl_xor_sync(0xffffffffu, s2, o);
    }
    float mu  = s1 * (1.f/128.f);
    float var = s2 * (1.f/128.f) - mu*mu;
    float rs  = rsqrtf(var + 1e-5f);
    float4 gva = *(const float4*)&gam[sub*8];
    float4 gvb = *(const float4*)&gam[sub*8+4];
    float4 bea = *(const float4*)&bet[sub*8];
    float4 beb = *(const float4*)&bet[sub*8+4];
    float gvv[8] = {gva.x,gva.y,gva.z,gva.w,gvb.x,gvb.y,gvb.z,gvb.w};
    float bev[8] = {bea.x,bea.y,bea.z,bea.w,beb.x,beb.y,beb.z,beb.w};
    float ov[8];
    #pragma unroll
    for (int i=0;i<8;i++) ov[i] = (ra[i]-mu)*rs*gvv[i] + bev[i];
    if (nv){
        float4 oa = make_float4(ov[0],ov[1],ov[2],ov[3]);
        float4 ob = make_float4(ov[4],ov[5],ov[6],ov[7]);
        *(float4*)&ho[node*128 + sub*8]     = oa;
        *(float4*)&ho[node*128 + sub*8 + 4] = ob;
    }
    if (conv){
        float4 a0a = nv ? *(const float4*)&g_h0[node*128 + sub*8]     : make_float4(0.f,0.f,0.f,0.f);
        float4 a0b = nv ? *(const float4*)&g_h0[node*128 + sub*8 + 4] : make_float4(0.f,0.f,0.f,0.f);
        float a0[8] = {a0a.x,a0a.y,a0a.z,a0a.w,a0b.x,a0b.y,a0b.z,a0b.w};
        float lg[5];
        #pragma unroll
        for (int c=0;c<5;c++){
            const float* w = &sCW[c*384];
            float4 b0a = *(const float4*)&w[sub*8];
            float4 b0b = *(const float4*)&w[sub*8+4];
            float4 b1a = *(const float4*)&w[128 + sub*8];
            float4 b1b = *(const float4*)&w[128 + sub*8+4];
            float4 b2a = *(const float4*)&w[256 + sub*8];
            float4 b2b = *(const float4*)&w[256 + sub*8+4];
            float w0[8] = {b0a.x,b0a.y,b0a.z,b0a.w,b0b.x,b0b.y,b0b.z,b0b.w};
            float w1[8] = {b1a.x,b1a.y,b1a.z,b1a.w,b1b.x,b1b.y,b1b.z,b1b.w};
            float w2[8] = {b2a.x,b2a.y,b2a.z,b2a.w,b2b.x,b2b.y,b2b.z,b2b.w};
            float p = 0.f;
            #pragma unroll
            for (int i=0;i<8;i++){
                p = fmaf(a0[i],  w0[i], p);
                p = fmaf(hvv[i], w1[i], p);
                p = fmaf(ov[i],  w2[i], p);
            }
            #pragma unroll
            for (int o=8;o>0;o>>=1) p += __shfl_xor_sync(0xffffffffu, p, o);
            lg[c] = p + sCB[c];
        }
        if (sub == 0 && nv){
            float m = lg[0];
            #pragma unroll
            for (int c=1;c<5;c++) m = fmaxf(m, lg[c]);
            float s = 0.f;
            #pragma unroll
            for (int c=0;c<5;c++) s += __expf(lg[c]-m);
            float ls = logf(s);
            #pragma unroll
            for (int c=0;c<5;c++) out[node*5+c] = lg[c]-m-ls;
        }
    }
}

// ---------------- conv2 GEMM + fused attention dots (fp16 xs output) ----------------
__global__ void __launch_bounds__(256) k_node2(const float* __restrict__ lin,
                                               const float* __restrict__ asv,
                                               const float* __restrict__ adv){
    __shared__ float sA[16*132];
    __shared__ float sB[16*132];
    int tid = threadIdx.x;
    int tx = tid & 15, ty = tid >> 4;
    int n0 = blockIdx.x*128;
    unsigned long long acc[8][4];
    #pragma unroll
    for (int r=0;r<8;r++)
        #pragma unroll
        for (int p=0;p<4;p++) acc[r][p] = 0ULL;
    for (int kc=0;kc<8;kc++){
        __syncthreads();
        #pragma unroll
        for (int t=tid;t<512;t+=256){
            int r = t>>2, q = t&3;
            int node = n0 + r;
            float4 v = (node<NN) ? *(const float4*)&g_h1[node*128 + kc*16 + q*4]
                                 : make_float4(0.f,0.f,0.f,0.f);
            sA[(q*4+0)*132+r]=v.x; sA[(q*4+1)*132+r]=v.y;
            sA[(q*4+2)*132+r]=v.z; sA[(q*4+3)*132+r]=v.w;
        }
        #pragma unroll
        for (int t=tid;t<512;t+=256){
            int d = t>>2, q = t&3;
            float4 v = *(const float4*)&lin[d*128 + kc*16 + q*4];
            sB[(q*4+0)*132+d]=v.x; sB[(q*4+1)*132+d]=v.y;
            sB[(q*4+2)*132+d]=v.z; sB[(q*4+3)*132+d]=v.w;
        }
        __syncthreads();
        #pragma unroll
        for (int k=0;k<16;k++){
            float4 a0 = *(const float4*)&sA[k*132 + ty*8];
            float4 a1 = *(const float4*)&sA[k*132 + ty*8 + 4];
            ulonglong2 b0 = *(const ulonglong2*)&sB[k*132 + tx*8];
            ulonglong2 b1 = *(const ulonglong2*)&sB[k*132 + tx*8 + 4];
            unsigned long long bp0=b0.x, bp1=b0.y, bp2=b1.x, bp3=b1.y;
            float ar[8] = {a0.x,a0.y,a0.z,a0.w,a1.x,a1.y,a1.z,a1.w};
            #pragma unroll
            for (int r=0;r<8;r++){
                unsigned long long a2 = pack2(ar[r]);
                fma2(acc[r][0], a2, bp0);
                fma2(acc[r][1], a2, bp1);
                fma2(acc[r][2], a2, bp2);
                fma2(acc[r][3], a2, bp3);
            }
        }
    }
    float4 ws0 = *(const float4*)&asv[tx*8];
    float4 ws1 = *(const float4*)&asv[tx*8+4];
    float4 wd0 = *(const float4*)&adv[tx*8];
    float4 wd1 = *(const float4*)&adv[tx*8+4];
    int hh = tx >> 2;
    #pragma unroll
    for (int r=0;r<8;r++){
        int node = n0 + ty*8 + r;
        if (node < NN){
            float f0=lo2(acc[r][0]), f1=hi2(acc[r][0]);
            float f2=lo2(acc[r][1]), f3=hi2(acc[r][1]);
            float f4=lo2(acc[r][2]), f5=hi2(acc[r][2]);
            float f6=lo2(acc[r][3]), f7=hi2(acc[r][3]);
            uint4 st;
            st.x = h2u(__floats2half2_rn(f0, f1));
            st.y = h2u(__floats2half2_rn(f2, f3));
            st.z = h2u(__floats2half2_rn(f4, f5));
            st.w = h2u(__floats2half2_rn(f6, f7));
            *(uint4*)(((char*)g_xsh) + node*256 + tx*16) = st;
            float s = f0*ws0.x + f1*ws0.y + f2*ws0.z + f3*ws0.w
                    + f4*ws1.x + f5*ws1.y + f6*ws1.z + f7*ws1.w;
            float d = f0*wd0.x + f1*wd0.y + f2*wd0.z + f3*wd0.w
                    + f4*wd1.x + f5*wd1.y + f6*wd1.z + f7*wd1.w;
            s += __shfl_xor_sync(0xffffffffu, s, 1);
            s += __shfl_xor_sync(0xffffffffu, s, 2);
            d += __shfl_xor_sync(0xffffffffu, d, 1);
            d += __shfl_xor_sync(0xffffffffu, d, 2);
            if ((tx & 3) == 0){
                g_asrc[node*4+hh] = s;
                g_adst[node*4+hh] = d;
            }
        }
    }
}

// ---------------- launcher ----------------
extern "C" void kernel_launch(void* const* d_in, const int* in_sizes, int n_in,
                              void* d_out, int out_size){
    const float* x      = (const float*)d_in[0];
    const int*   ei     = (const int*)  d_in[1];
    const float* ea     = (const float*)d_in[2];
    const float* ee_w1  = (const float*)d_in[3];
    const float* ee_b1  = (const float*)d_in[4];
    const float* ee_w2  = (const float*)d_in[5];
    const float* ee_b2  = (const float*)d_in[6];
    const float* proj_w = (const float*)d_in[7];
    const float* proj_b = (const float*)d_in[8];
    const float* c1_lin = (const float*)d_in[9];
    const float* c1_as  = (const float*)d_in[10];
    const float* c1_ad  = (const float*)d_in[11];
    const float* c1_le  = (const float*)d_in[12];
    const float* c1_ae  = (const float*)d_in[13];
    const float* c1_b   = (const float*)d_in[14];
    const float* c2_lin = (const float*)d_in[15];
    const float* c2_as  = (const float*)d_in[16];
    const float* c2_ad  = (const float*)d_in[17];
    const float* c2_le  = (const float*)d_in[18];
    const float* c2_ae  = (const float*)d_in[19];
    const float* c2_b   = (const float*)d_in[20];
    const float* n1_g   = (const float*)d_in[21];
    const float* n1_b   = (const float*)d_in[22];
    const float* n2_g   = (const float*)d_in[23];
    const float* n2_b   = (const float*)d_in[24];
    const float* jk_w   = (const float*)d_in[25];
    const float* jk_b   = (const float*)d_in[26];
    const float* cls_w  = (const float*)d_in[27];
    const float* cls_b  = (const float*)d_in[28];
    float* out = (float*)d_out;

    k_fused1<<<B_HIST+B_CW+1+B_NODE1,256>>>(ei, c1_le, c1_ae, c2_le, c2_ae,
                                            cls_w, cls_b, jk_w, jk_b,
                                            x, proj_w, proj_b, c1_lin, c1_as, c1_ad);
    k_scanab<<<98,512>>>();
    k_scanc<<<98,512>>>();
    k_edge<<<(QSTRIDE2+255)/256,256>>>(ea, ei, ee_w1, ee_b1, ee_w2, ee_b2);
    k_gat<<<(NN+31)/32,512>>>(c1_b, n1_g, n1_b, 0, out);
    k_node2<<<(NN+127)/128,256>>>(c2_lin, c2_as, c2_ad);
    k_gat<<<(NN+31)/32,512>>>(c2_b, n2_g, n2_b, 1, out);
}

// round 17
// speedup vs baseline: 1.0542x; 1.0268x over previous
#include <cuda_runtime.h>
#include <cuda_fp16.h>
#include <math.h>

#define NN 50000
#define EE 800000

// ---------------- scratch (device globals; zero-initialized at load) ----------------
__device__ uint4  g_rec1[EE];     // conv1 edge record: {src, half2(ae01), half2(ae23), 0} CSR order
__device__ uint4  g_rec2[EE];     // conv2 edge record
__device__ int    g_cnt[NN];      // invariant: zero at entry (k_scan re-zeroes)
__device__ int    g_cur[NN];
__device__ int    g_rowptr[NN+1];
__device__ int    g_part[128];
__device__ int    g_c1, g_c2;     // invariant: zero at entry (self-resetting)
__device__ volatile int g_flag;   // invariant: zero at entry (self-resetting)
__device__ float  g_h0[NN*128];
__device__ float  g_h1[NN*128];
__device__ float  g_h2[NN*128];
__device__ __half g_xsh[NN*128];  // fp16 transformed features (gather source)
__device__ float  g_asrc[NN*4];
__device__ float  g_adst[NN*4];
__device__ float  g_M[32];        // [conv*16 + j*4 + h]
__device__ float  g_CW[5*384];    // collapsed classifier: cls_w @ jk_w
__device__ float  g_cb2[5];       // collapsed bias

// ---------------- helpers ----------------
__device__ __forceinline__ unsigned long long pack2(float x){
    unsigned long long r;
    unsigned int u = __float_as_uint(x);
    asm("mov.b64 %0, {%1, %1};" : "=l"(r) : "r"(u));
    return r;
}
__device__ __forceinline__ void fma2(unsigned long long& acc,
                                     unsigned long long a, unsigned long long b){
    asm("fma.rn.f32x2 %0, %1, %2, %0;" : "+l"(acc) : "l"(a), "l"(b));
}
__device__ __forceinline__ float lo2(unsigned long long v){
    unsigned int a, b;
    asm("mov.b64 {%0, %1}, %2;" : "=r"(a), "=r"(b) : "l"(v));
    return __uint_as_float(a);
}
__device__ __forceinline__ float hi2(unsigned long long v){
    unsigned int a, b;
    asm("mov.b64 {%0, %1}, %2;" : "=r"(a), "=r"(b) : "l"(v));
    return __uint_as_float(b);
}
__device__ __forceinline__ unsigned h2u(__half2 h){
    return *reinterpret_cast<unsigned*>(&h);
}
__device__ __forceinline__ __half2 u2h(unsigned u){
    return *reinterpret_cast<__half2*>(&u);
}

// ============ launch 1: hist + CW-prep + M-prep + node1, fused ============
#define B_HIST 782
#define B_CW   241
#define B_NODE1 1563

__global__ void __launch_bounds__(256) k_fused1(
        const int* __restrict__ ei,
        const float* __restrict__ le1, const float* __restrict__ ae1,
        const float* __restrict__ le2, const float* __restrict__ ae2,
        const float* __restrict__ cw,  const float* __restrict__ cb,
        const float* __restrict__ jkw, const float* __restrict__ jkb,
        const float* __restrict__ x,
        const float* __restrict__ pw, const float* __restrict__ pb,
        const float* __restrict__ lw,
        const float* __restrict__ asv, const float* __restrict__ adv){
    int b = blockIdx.x;
    if (b < B_HIST){
        int t = b*256 + threadIdx.x;
        if (t < EE/4){
            int4 d4 = ((const int4*)(ei+EE))[t];
            atomicAdd(&g_cnt[d4.x], 1);
            atomicAdd(&g_cnt[d4.y], 1);
            atomicAdd(&g_cnt[d4.z], 1);
            atomicAdd(&g_cnt[d4.w], 1);
        }
        return;
    }
    if (b < B_HIST + B_CW){
        int w = (b-B_HIST)*8 + (threadIdx.x >> 5);
        int lane = threadIdx.x & 31;
        if (w >= 5*385) return;
        int c = w / 385, j = w % 385;
        float4 a = *(const float4*)&cw[c*128 + lane*4];
        int d = lane*4;
        float s;
        if (j < 384){
            s = a.x*jkw[(d+0)*384+j] + a.y*jkw[(d+1)*384+j]
              + a.z*jkw[(d+2)*384+j] + a.w*jkw[(d+3)*384+j];
        } else {
            float4 bb = *(const float4*)&jkb[d];
            s = a.x*bb.x + a.y*bb.y + a.z*bb.z + a.w*bb.w;
        }
        #pragma unroll
        for (int o=16;o>0;o>>=1) s += __shfl_xor_sync(0xffffffffu, s, o);
        if (lane == 0){
            if (j < 384) g_CW[c*384+j] = s;
            else         g_cb2[c] = s + cb[c];
        }
        return;
    }
    if (b == B_HIST + B_CW){
        int t = threadIdx.x;
        if (t < 32){
            int which = t >> 4, j = (t >> 2) & 3, h = t & 3;
            const float* le = which ? le2 : le1;
            const float* ae = which ? ae2 : ae1;
            float s = 0.f;
            for (int c = 0; c < 32; c++)
                s += le[(h*32+c)*4 + j] * ae[h*32+c];
            g_M[which*16 + j*4 + h] = s;
        }
        return;
    }
    // ---- node1: two independent 128-thread halves ----
    __shared__ __align__(16) float sx[2][16*20];
    int tid = threadIdx.x;
    int sub = tid >> 7, stid = tid & 127;
    int n0 = (b - (B_HIST+B_CW+1))*32 + sub*16;
    float attS = asv[stid], attD = adv[stid], pbd = pb[stid];
    float wp[16], wl[16];
    #pragma unroll
    for (int q=0;q<4;q++){
        float4 a = *(const float4*)&pw[stid*16 + q*4];
        wp[q*4+0]=a.x; wp[q*4+1]=a.y; wp[q*4+2]=a.z; wp[q*4+3]=a.w;
        float4 bb = *(const float4*)&lw[stid*16 + q*4];
        wl[q*4+0]=bb.x; wl[q*4+1]=bb.y; wl[q*4+2]=bb.z; wl[q*4+3]=bb.w;
    }
    for (int i=stid;i<256;i+=128){
        int n=i>>4, k=i&15;
        int node=n0+n;
        sx[sub][n*20+k] = (node<NN) ? x[node*16+k] : 0.f;
    }
    __syncthreads();
    float acc0[16], acc1[16];
    #pragma unroll
    for (int n=0;n<16;n++){ acc0[n]=pbd; acc1[n]=0.f; }
    #pragma unroll
    for (int n=0;n<16;n++){
        float4 x0 = *(const float4*)&sx[sub][n*20];
        float4 x1 = *(const float4*)&sx[sub][n*20+4];
        float4 x2 = *(const float4*)&sx[sub][n*20+8];
        float4 x3 = *(const float4*)&sx[sub][n*20+12];
        float xv[16] = {x0.x,x0.y,x0.z,x0.w, x1.x,x1.y,x1.z,x1.w,
                        x2.x,x2.y,x2.z,x2.w, x3.x,x3.y,x3.z,x3.w};
        #pragma unroll
        for (int k=0;k<16;k++){
            acc0[n] = fmaf(xv[k], wp[k], acc0[n]);
            acc1[n] = fmaf(xv[k], wl[k], acc1[n]);
        }
    }
    int lane = stid&31, h = stid>>5;
    for (int n=0;n<16;n++){
        int node=n0+n;
        if (node>=NN) break;
        g_h0[node*128+stid]  = acc0[n];
        g_xsh[node*128+stid] = __float2half(acc1[n]);
        float s = acc1[n]*attS, dd = acc1[n]*attD;
        #pragma unroll
        for (int o=16;o>0;o>>=1){
            s  += __shfl_down_sync(0xffffffffu, s, o);
            dd += __shfl_down_sync(0xffffffffu, dd, o);
        }
        if (lane==0){ g_asrc[node*4+h]=s; g_adst[node*4+h]=dd; }
    }
}

// ---------------- merged scan: single launch, flag-spin grid sync (98 blocks, all resident) ----------------
__global__ void __launch_bounds__(512) k_scan(){
    __shared__ int sred[16];
    __shared__ int amlast;
    __shared__ int sb[128];
    __shared__ int soff;
    __shared__ int s[512];
    int t = threadIdx.x;
    int gidx = blockIdx.x*512 + t;
    int v = (gidx < NN) ? g_cnt[gidx] : 0;
    int w = v;
    #pragma unroll
    for (int o=16;o>0;o>>=1) w += __shfl_xor_sync(0xffffffffu, w, o);
    int lane = t & 31, wid = t >> 5;
    if (lane == 0) sred[wid] = w;
    __syncthreads();
    if (t < 16){
        w = sred[t];
        #pragma unroll
        for (int o=8;o>0;o>>=1) w += __shfl_xor_sync(0xffffu, w, o);
    }
    if (t == 0){
        g_part[blockIdx.x] = w;
        __threadfence();
        int n = atomicAdd(&g_c1, 1);
        amlast = (n == 97);
        if (amlast) g_c1 = 0;      // restore zero-invariant
    }
    __syncthreads();
    if (amlast){
        __threadfence();
        int vv = 0;
        if (t < 128){
            vv = (t < 98) ? g_part[t] : 0;
            sb[t] = vv;
        }
        __syncthreads();
        for (int off=1; off<128; off<<=1){
            int u = (t >= off && t < 128) ? sb[t-off] : 0;
            __syncthreads();
            if (t < 128) sb[t] += u;
            __syncthreads();
        }
        if (t < 98) g_part[t] = sb[t] - vv;   // exclusive
        __threadfence();
        __syncthreads();
        if (t == 0) g_flag = 1;
    }
    if (t == 0){
        while (g_flag == 0) { }
        __threadfence();
        soff = g_part[blockIdx.x];
    }
    __syncthreads();
    int off0 = soff;
    s[t] = v;
    __syncthreads();
    for (int off=1; off<512; off<<=1){
        int u = (t >= off) ? s[t-off] : 0;
        __syncthreads();
        s[t] += u;
        __syncthreads();
    }
    int excl = s[t] - v + off0;
    if (gidx < NN){
        g_rowptr[gidx] = excl;
        g_cur[gidx]    = excl;
        g_cnt[gidx]    = 0;                // restore zero-invariant
        if (gidx == NN-1) g_rowptr[NN] = excl + v;
    }
    __syncthreads();
    if (t == 0){
        int n2 = atomicAdd(&g_c2, 1);
        if (n2 == 97){ g_c2 = 0; g_flag = 0; }   // restore zero-invariants
    }
}

// ---------------- edge encoder: 2 edges/thread in half2 lanes, packed records ----------------
#define QSTRIDE2 400000   // EE/2
__global__ void __launch_bounds__(256) k_edge(
        const float* __restrict__ ea, const int* __restrict__ ei,
        const float* __restrict__ w1, const float* __restrict__ b1,
        const float* __restrict__ w2, const float* __restrict__ b2){
    __shared__ __align__(16) unsigned sw1h[256];   // dup half2(w1)
    __shared__ unsigned sb1h[32];                  // dup half2(b1)
    __shared__ __align__(16) unsigned sWM1h[128];  // dup half2 [c][h]
    __shared__ __align__(16) unsigned sWM2h[128];
    __shared__ float sR0[8];
    int tid = threadIdx.x;
    if (tid < 256) sw1h[tid] = h2u(__float2half2_rn(w1[tid]));
    if (tid < 32)  sb1h[tid] = h2u(__float2half2_rn(b1[tid]));
    if (tid < 128){
        int c = tid >> 2, h = tid & 3;
        float s1 = 0.f, s2 = 0.f;
        #pragma unroll
        for (int j=0;j<4;j++){
            float wv = w2[j*32+c];
            s1 = fmaf(wv, g_M[j*4+h],    s1);
            s2 = fmaf(wv, g_M[16+j*4+h], s2);
        }
        sWM1h[c*4+h] = h2u(__float2half2_rn(s1));
        sWM2h[c*4+h] = h2u(__float2half2_rn(s2));
    }
    if (tid >= 128 && tid < 136){
        int which = (tid-128) >> 2, h = tid & 3;
        float s = 0.f;
        #pragma unroll
        for (int j=0;j<4;j++) s = fmaf(b2[j], g_M[which*16+j*4+h], s);
        sR0[tid-128] = s;
    }
    __syncthreads();
    int gid = blockIdx.x*256 + tid;
    if (gid >= QSTRIDE2) return;
    int ee1 = gid + QSTRIDE2;
    float4 A0a = ((const float4*)ea)[gid*2];
    float4 A0b = ((const float4*)ea)[gid*2+1];
    float4 A1a = ((const float4*)ea)[ee1*2];
    float4 A1b = ((const float4*)ea)[ee1*2+1];
    __half2 av[8];
    av[0] = __floats2half2_rn(A0a.x, A1a.x);
    av[1] = __floats2half2_rn(A0a.y, A1a.y);
    av[2] = __floats2half2_rn(A0a.z, A1a.z);
    av[3] = __floats2half2_rn(A0a.w, A1a.w);
    av[4] = __floats2half2_rn(A0b.x, A1b.x);
    av[5] = __floats2half2_rn(A0b.y, A1b.y);
    av[6] = __floats2half2_rn(A0b.z, A1b.z);
    av[7] = __floats2half2_rn(A0b.w, A1b.w);
    __half2 r1h[4], r2h[4];
    #pragma unroll
    for (int k=0;k<4;k++){
        r1h[k] = __float2half2_rn(sR0[k]);
        r2h[k] = __float2half2_rn(sR0[4+k]);
    }
    const __half2 zero2 = __float2half2_rn(0.f);
    #pragma unroll
    for (int c=0;c<32;c++){
        uint4 wv0 = *(const uint4*)&sw1h[c*8];
        uint4 wv1 = *(const uint4*)&sw1h[c*8+4];
        __half2 hv = u2h(sb1h[c]);
        hv = __hfma2(u2h(wv0.x), av[0], hv);
        hv = __hfma2(u2h(wv0.y), av[1], hv);
        hv = __hfma2(u2h(wv0.z), av[2], hv);
        hv = __hfma2(u2h(wv0.w), av[3], hv);
        hv = __hfma2(u2h(wv1.x), av[4], hv);
        hv = __hfma2(u2h(wv1.y), av[5], hv);
        hv = __hfma2(u2h(wv1.z), av[6], hv);
        hv = __hfma2(u2h(wv1.w), av[7], hv);
        hv = __hmax2(hv, zero2);
        uint4 m1 = *(const uint4*)&sWM1h[c*4];
        uint4 m2 = *(const uint4*)&sWM2h[c*4];
        r1h[0] = __hfma2(u2h(m1.x), hv, r1h[0]);
        r1h[1] = __hfma2(u2h(m1.y), hv, r1h[1]);
        r1h[2] = __hfma2(u2h(m1.z), hv, r1h[2]);
        r1h[3] = __hfma2(u2h(m1.w), hv, r1h[3]);
        r2h[0] = __hfma2(u2h(m2.x), hv, r2h[0]);
        r2h[1] = __hfma2(u2h(m2.y), hv, r2h[1]);
        r2h[2] = __hfma2(u2h(m2.z), hv, r2h[2]);
        r2h[3] = __hfma2(u2h(m2.w), hv, r2h[3]);
    }
    // edge 0 scatter (low halves) — packed records, 2 random sectors
    {
        int srcn = ei[gid], d = ei[EE+gid];
        int pos = atomicAdd(&g_cur[d], 1);
        uint4 rc1, rc2;
        rc1.x = (unsigned)srcn;
        rc1.y = h2u(__lows2half2(r1h[0], r1h[1]));
        rc1.z = h2u(__lows2half2(r1h[2], r1h[3]));
        rc1.w = 0u;
        rc2.x = (unsigned)srcn;
        rc2.y = h2u(__lows2half2(r2h[0], r2h[1]));
        rc2.z = h2u(__lows2half2(r2h[2], r2h[3]));
        rc2.w = 0u;
        g_rec1[pos] = rc1;
        g_rec2[pos] = rc2;
    }
    // edge 1 scatter (high halves)
    {
        int srcn = ei[ee1], d = ei[EE+ee1];
        int pos = atomicAdd(&g_cur[d], 1);
        uint4 rc1, rc2;
        rc1.x = (unsigned)srcn;
        rc1.y = h2u(__highs2half2(r1h[0], r1h[1]));
        rc1.z = h2u(__highs2half2(r1h[2], r1h[3]));
        rc1.w = 0u;
        rc2.x = (unsigned)srcn;
        rc2.y = h2u(__highs2half2(r2h[0], r2h[1]));
        rc2.z = h2u(__highs2half2(r2h[2], r2h[3]));
        rc2.w = 0u;
        g_rec1[pos] = rc1;
        g_rec2[pos] = rc2;
    }
}

// ---------------- fused GAT conv: 2 nodes/warp, record-based phase1, HFMA2 gather ----------------
__global__ void __launch_bounds__(512) k_gat(const float* __restrict__ bias,
                      const float* __restrict__ gam,
                      const float* __restrict__ bet, int conv,
                      float* __restrict__ out){
    __shared__ float2 sp[16][2][68];   // [warp][half][h*17 + j]
    __shared__ float sCW[1920];
    __shared__ float sCB[5];
    int tid = threadIdx.x;
    if (conv){
        for (int i=tid;i<1920;i+=512) sCW[i] = g_CW[i];
        if (tid < 5) sCB[tid] = g_cb2[tid];
    }
    __syncthreads();
    int wid = tid >> 5, lane = tid & 31;
    int half = lane >> 4, sub = lane & 15;
    int node = blockIdx.x*32 + wid*2 + half;
    bool nv = node < NN;
    int h = sub >> 2;                      // head of this lane's 8 dims
    const uint4* __restrict__ rec    = conv ? g_rec2 : g_rec1;
    const float4* __restrict__ asrc4 = (const float4*)g_asrc;
    const char*   xbase = ((const char*)g_xsh) + sub*16;   // 8 halves per lane
    float4 ad = nv ? ((const float4*)g_adst)[node] : make_float4(0.f,0.f,0.f,0.f);
    int beg = nv ? g_rowptr[node]   : 0;
    int end = nv ? g_rowptr[node+1] : 0;
    int cnt = end - beg;
    int ocnt = __shfl_xor_sync(0xffffffffu, cnt, 16);
    int mx = cnt > ocnt ? cnt : ocnt;
    float4 den = make_float4(0.f,0.f,0.f,0.f);
    __half2 acc[4];
    acc[0]=acc[1]=acc[2]=acc[3]=__float2half2_rn(0.f);
    float2* myp = sp[wid][half];
    for (int b = 0; b < mx; b += 16){
        int j0 = b + sub;
        bool v = j0 < cnt;
        int cidx = v ? (beg + j0) : (end > beg ? end-1 : 0);
        uint4 rr = rec[cidx];
        int s = (int)rr.x;
        float4 w = make_float4(0.f,0.f,0.f,0.f);
        if (v){
            float2 a01 = __half22float2(u2h(rr.y));
            float2 a23 = __half22float2(u2h(rr.z));
            float4 as = asrc4[s];
            float ax = as.x+ad.x+a01.x; ax = ax>0.f?ax:0.2f*ax;
            float ay = as.y+ad.y+a01.y; ay = ay>0.f?ay:0.2f*ay;
            float az = as.z+ad.z+a23.x; az = az>0.f?az:0.2f*az;
            float aw = as.w+ad.w+a23.y; aw = aw>0.f?aw:0.2f*aw;
            w = make_float4(__expf(ax), __expf(ay), __expf(az), __expf(aw));
        }
        den.x += w.x; den.y += w.y; den.z += w.z; den.w += w.w;
        float so = __uint_as_float((unsigned)s * 256u);   // byte offset of fp16 row
        __syncwarp();
        myp[sub]      = make_float2(so, __uint_as_float(h2u(__float2half2_rn(w.x))));
        myp[17 + sub] = make_float2(so, __uint_as_float(h2u(__float2half2_rn(w.y))));
        myp[34 + sub] = make_float2(so, __uint_as_float(h2u(__float2half2_rn(w.z))));
        myp[51 + sub] = make_float2(so, __uint_as_float(h2u(__float2half2_rn(w.w))));
        __syncwarp();
        int jm = mx - b; if (jm > 16) jm = 16;
        const float2* hp2 = &myp[h*17];
        for (int c = 0; c < jm; c += 8){
            #pragma unroll
            for (int j = 0; j < 8; j++){
                float2 e2 = hp2[c+j];
                uint4 xr = *(const uint4*)(xbase + __float_as_uint(e2.x));
                unsigned wb = __float_as_uint(e2.y);
                __half2 wh = *reinterpret_cast<__half2*>(&wb);
                acc[0] = __hfma2(*reinterpret_cast<__half2*>(&xr.x), wh, acc[0]);
                acc[1] = __hfma2(*reinterpret_cast<__half2*>(&xr.y), wh, acc[1]);
                acc[2] = __hfma2(*reinterpret_cast<__half2*>(&xr.z), wh, acc[2]);
                acc[3] = __hfma2(*reinterpret_cast<__half2*>(&xr.w), wh, acc[3]);
            }
        }
    }
    // den reduce within half-warp (offsets < 16 keep halves separate)
    #pragma unroll
    for (int o=8;o>0;o>>=1){
        den.x += __shfl_xor_sync(0xffffffffu, den.x, o);
        den.y += __shfl_xor_sync(0xffffffffu, den.y, o);
        den.z += __shfl_xor_sync(0xffffffffu, den.z, o);
        den.w += __shfl_xor_sync(0xffffffffu, den.w, o);
    }
    float dh = (h==0)?den.x:(h==1)?den.y:(h==2)?den.z:den.w;
    float inv = 1.f/(dh + 1e-16f);
    const float* hp = conv ? g_h1 : g_h0;
    float*       ho = conv ? g_h2 : g_h1;
    float4 hva = nv ? *(const float4*)&hp[node*128 + sub*8]     : make_float4(0.f,0.f,0.f,0.f);
    float4 hvb = nv ? *(const float4*)&hp[node*128 + sub*8 + 4] : make_float4(0.f,0.f,0.f,0.f);
    float4 bva = *(const float4*)&bias[sub*8];
    float4 bvb = *(const float4*)&bias[sub*8+4];
    float2 f0 = __half22float2(acc[0]);
    float2 f1 = __half22float2(acc[1]);
    float2 f2 = __half22float2(acc[2]);
    float2 f3 = __half22float2(acc[3]);
    float fa[8] = {f0.x,f0.y,f1.x,f1.y,f2.x,f2.y,f3.x,f3.y};
    float hvv[8] = {hva.x,hva.y,hva.z,hva.w,hvb.x,hvb.y,hvb.z,hvb.w};
    float bvv[8] = {bva.x,bva.y,bva.z,bva.w,bvb.x,bvb.y,bvb.z,bvb.w};
    float ra[8];
    float s1 = 0.f, s2 = 0.f;
    #pragma unroll
    for (int i=0;i<8;i++){
        float r = fa[i]*inv + bvv[i];
        r = (r>0.f) ? r : (__expf(r)-1.f);
        r += hvv[i];
        ra[i] = r;
        s1 += r; s2 += r*r;
    }
    #pragma unroll
    for (int o=8;o>0;o>>=1){
        s1 += __shfl_xor_sync(0xffffffffu, s1, o);
        s2 += __shfl_xor_sync(0xffffffffu, s2, o);
    }
    float mu  = s1 * (1.f/128.f);
    float var = s2 * (1.f/128.f) - mu*mu;
    float rs  = rsqrtf(var + 1e-5f);
    float4 gva = *(const float4*)&gam[sub*8];
    float4 gvb = *(const float4*)&gam[sub*8+4];
    float4 bea = *(const float4*)&bet[sub*8];
    float4 beb = *(const float4*)&bet[sub*8+4];
    float gvv[8] = {gva.x,gva.y,gva.z,gva.w,gvb.x,gvb.y,gvb.z,gvb.w};
    float bev[8] = {bea.x,bea.y,bea.z,bea.w,beb.x,beb.y,beb.z,beb.w};
    float ov[8];
    #pragma unroll
    for (int i=0;i<8;i++) ov[i] = (ra[i]-mu)*rs*gvv[i] + bev[i];
    if (nv){
        float4 oa = make_float4(ov[0],ov[1],ov[2],ov[3]);
        float4 ob = make_float4(ov[4],ov[5],ov[6],ov[7]);
        *(float4*)&ho[node*128 + sub*8]     = oa;
        *(float4*)&ho[node*128 + sub*8 + 4] = ob;
    }
    if (conv){
        float4 a0a = nv ? *(const float4*)&g_h0[node*128 + sub*8]     : make_float4(0.f,0.f,0.f,0.f);
        float4 a0b = nv ? *(const float4*)&g_h0[node*128 + sub*8 + 4] : make_float4(0.f,0.f,0.f,0.f);
        float a0[8] = {a0a.x,a0a.y,a0a.z,a0a.w,a0b.x,a0b.y,a0b.z,a0b.w};
        float lg[5];
        #pragma unroll
        for (int c=0;c<5;c++){
            const float* w = &sCW[c*384];
            float4 b0a = *(const float4*)&w[sub*8];
            float4 b0b = *(const float4*)&w[sub*8+4];
            float4 b1a = *(const float4*)&w[128 + sub*8];
            float4 b1b = *(const float4*)&w[128 + sub*8+4];
            float4 b2a = *(const float4*)&w[256 + sub*8];
            float4 b2b = *(const float4*)&w[256 + sub*8+4];
            float w0[8] = {b0a.x,b0a.y,b0a.z,b0a.w,b0b.x,b0b.y,b0b.z,b0b.w};
            float w1[8] = {b1a.x,b1a.y,b1a.z,b1a.w,b1b.x,b1b.y,b1b.z,b1b.w};
            float w2[8] = {b2a.x,b2a.y,b2a.z,b2a.w,b2b.x,b2b.y,b2b.z,b2b.w};
            float p = 0.f;
            #pragma unroll
            for (int i=0;i<8;i++){
                p = fmaf(a0[i],  w0[i], p);
                p = fmaf(hvv[i], w1[i], p);
                p = fmaf(ov[i],  w2[i], p);
            }
            #pragma unroll
            for (int o=8;o>0;o>>=1) p += __shfl_xor_sync(0xffffffffu, p, o);
            lg[c] = p + sCB[c];
        }
        if (sub == 0 && nv){
            float m = lg[0];
            #pragma unroll
            for (int c=1;c<5;c++) m = fmaxf(m, lg[c]);
            float s = 0.f;
            #pragma unroll
            for (int c=0;c<5;c++) s += __expf(lg[c]-m);
            float ls = logf(s);
            #pragma unroll
            for (int c=0;c<5;c++) out[node*5+c] = lg[c]-m-ls;
        }
    }
}

// ---------------- conv2 GEMM + fused attention dots (fp16 xs output) ----------------
__global__ void __launch_bounds__(256) k_node2(const float* __restrict__ lin,
                                               const float* __restrict__ asv,
                                               const float* __restrict__ adv){
    __shared__ float sA[16*132];
    __shared__ float sB[16*132];
    int tid = threadIdx.x;
    int tx = tid & 15, ty = tid >> 4;
    int n0 = blockIdx.x*128;
    unsigned long long acc[8][4];
    #pragma unroll
    for (int r=0;r<8;r++)
        #pragma unroll
        for (int p=0;p<4;p++) acc[r][p] = 0ULL;
    for (int kc=0;kc<8;kc++){
        __syncthreads();
        #pragma unroll
        for (int t=tid;t<512;t+=256){
            int r = t>>2, q = t&3;
            int node = n0 + r;
            float4 v = (node<NN) ? *(const float4*)&g_h1[node*128 + kc*16 + q*4]
                                 : make_float4(0.f,0.f,0.f,0.f);
            sA[(q*4+0)*132+r]=v.x; sA[(q*4+1)*132+r]=v.y;
            sA[(q*4+2)*132+r]=v.z; sA[(q*4+3)*132+r]=v.w;
        }
        #pragma unroll
        for (int t=tid;t<512;t+=256){
            int d = t>>2, q = t&3;
            float4 v = *(const float4*)&lin[d*128 + kc*16 + q*4];
            sB[(q*4+0)*132+d]=v.x; sB[(q*4+1)*132+d]=v.y;
            sB[(q*4+2)*132+d]=v.z; sB[(q*4+3)*132+d]=v.w;
        }
        __syncthreads();
        #pragma unroll
        for (int k=0;k<16;k++){
            float4 a0 = *(const float4*)&sA[k*132 + ty*8];
            float4 a1 = *(const float4*)&sA[k*132 + ty*8 + 4];
            ulonglong2 b0 = *(const ulonglong2*)&sB[k*132 + tx*8];
            ulonglong2 b1 = *(const ulonglong2*)&sB[k*132 + tx*8 + 4];
            unsigned long long bp0=b0.x, bp1=b0.y, bp2=b1.x, bp3=b1.y;
            float ar[8] = {a0.x,a0.y,a0.z,a0.w,a1.x,a1.y,a1.z,a1.w};
            #pragma unroll
            for (int r=0;r<8;r++){
                unsigned long long a2 = pack2(ar[r]);
                fma2(acc[r][0], a2, bp0);
                fma2(acc[r][1], a2, bp1);
                fma2(acc[r][2], a2, bp2);
                fma2(acc[r][3], a2, bp3);
            }
        }
    }
    float4 ws0 = *(const float4*)&asv[tx*8];
    float4 ws1 = *(const float4*)&asv[tx*8+4];
    float4 wd0 = *(const float4*)&adv[tx*8];
    float4 wd1 = *(const float4*)&adv[tx*8+4];
    int hh = tx >> 2;
    #pragma unroll
    for (int r=0;r<8;r++){
        int node = n0 + ty*8 + r;
        if (node < NN){
            float f0=lo2(acc[r][0]), f1=hi2(acc[r][0]);
            float f2=lo2(acc[r][1]), f3=hi2(acc[r][1]);
            float f4=lo2(acc[r][2]), f5=hi2(acc[r][2]);
            float f6=lo2(acc[r][3]), f7=hi2(acc[r][3]);
            uint4 st;
            st.x = h2u(__floats2half2_rn(f0, f1));
            st.y = h2u(__floats2half2_rn(f2, f3));
            st.z = h2u(__floats2half2_rn(f4, f5));
            st.w = h2u(__floats2half2_rn(f6, f7));
            *(uint4*)(((char*)g_xsh) + node*256 + tx*16) = st;
            float s = f0*ws0.x + f1*ws0.y + f2*ws0.z + f3*ws0.w
                    + f4*ws1.x + f5*ws1.y + f6*ws1.z + f7*ws1.w;
            float d = f0*wd0.x + f1*wd0.y + f2*wd0.z + f3*wd0.w
                    + f4*wd1.x + f5*wd1.y + f6*wd1.z + f7*wd1.w;
            s += __shfl_xor_sync(0xffffffffu, s, 1);
            s += __shfl_xor_sync(0xffffffffu, s, 2);
            d += __shfl_xor_sync(0xffffffffu, d, 1);
            d += __shfl_xor_sync(0xffffffffu, d, 2);
            if ((tx & 3) == 0){
                g_asrc[node*4+hh] = s;
                g_adst[node*4+hh] = d;
            }
        }
    }
}

// ---------------- launcher ----------------
extern "C" void kernel_launch(void* const* d_in, const int* in_sizes, int n_in,
                              void* d_out, int out_size){
    const float* x      = (const float*)d_in[0];
    const int*   ei     = (const int*)  d_in[1];
    const float* ea     = (const float*)d_in[2];
    const float* ee_w1  = (const float*)d_in[3];
    const float* ee_b1  = (const float*)d_in[4];
    const float* ee_w2  = (const float*)d_in[5];
    const float* ee_b2  = (const float*)d_in[6];
    const float* proj_w = (const float*)d_in[7];
    const float* proj_b = (const float*)d_in[8];
    const float* c1_lin = (const float*)d_in[9];
    const float* c1_as  = (const float*)d_in[10];
    const float* c1_ad  = (const float*)d_in[11];
    const float* c1_le  = (const float*)d_in[12];
    const float* c1_ae  = (const float*)d_in[13];
    const float* c1_b   = (const float*)d_in[14];
    const float* c2_lin = (const float*)d_in[15];
    const float* c2_as  = (const float*)d_in[16];
    const float* c2_ad  = (const float*)d_in[17];
    const float* c2_le  = (const float*)d_in[18];
    const float* c2_ae  = (const float*)d_in[19];
    const float* c2_b   = (const float*)d_in[20];
    const float* n1_g   = (const float*)d_in[21];
    const float* n1_b   = (const float*)d_in[22];
    const float* n2_g   = (const float*)d_in[23];
    const float* n2_b   = (const float*)d_in[24];
    const float* jk_w   = (const float*)d_in[25];
    const float* jk_b   = (const float*)d_in[26];
    const float* cls_w  = (const float*)d_in[27];
    const float* cls_b  = (const float*)d_in[28];
    float* out = (float*)d_out;

    k_fused1<<<B_HIST+B_CW+1+B_NODE1,256>>>(ei, c1_le, c1_ae, c2_le, c2_ae,
                                            cls_w, cls_b, jk_w, jk_b,
                                            x, proj_w, proj_b, c1_lin, c1_as, c1_ad);
    k_scan<<<98,512>>>();
    k_edge<<<(QSTRIDE2+255)/256,256>>>(ea, ei, ee_w1, ee_b1, ee_w2, ee_b2);
    k_gat<<<(NN+31)/32,512>>>(c1_b, n1_g, n1_b, 0, out);   // profiled slot (4th)
    k_node2<<<(NN+127)/128,256>>>(c2_lin, c2_as, c2_ad);
    k_gat<<<(NN+31)/32,512>>>(c2_b, n2_g, n2_b, 1, out);
}